// round 3
// baseline (speedup 1.0000x reference)
#include <cuda_runtime.h>
#include <cuda_bf16.h>
#include <cstdint>

// ============================================================================
// Mean-field CRF on GB300 (sm_103a harness, but PTX target is plain sm_103:
// NO tcgen05 / 'a'-gated features. Tensor path = mma.sync m16n8k16 bf16).
//
//   K_sp, K_bl (8192x8192 Gaussian kernels) constant across 5 iterations:
//   build once (bf16, fragment-blocked layout), then per iteration:
//     q = unaries + (A_sp p) K_sp + (A_bl p) K_bl,  A_* = -(compat @ W_*)
//   GEMM: A-operand = class vectors P (m16 = padded classes), B = K blocks.
// ============================================================================

#define DI __device__ __forceinline__

static constexpr int   NPT   = 8192;
static constexpr int   NC    = 10;
static constexpr int   CP    = 16;                 // padded classes (mma m16)
static constexpr int   NSLICE = 8;                 // split-K slices
static constexpr float LOG2E = 1.4426950408889634f;
static constexpr float ESP   = LOG2E / 64.0f;      // spatial: /theta_gamma^2
static constexpr float EBL   = LOG2E;

// ---- static device scratch (no allocations) --------------------------------
// K stored fragment-blocked: block = (i-tile of 8) x (j-superchunk of 32),
// 512B per block: lane = (i&7)*4 + ((j>>1)&3), then 4 regs of bf16x2:
// reg = (j>>3)&3, low/high = j&1.
__device__ __align__(1024) __nv_bfloat16 g_Ksp[(size_t)NPT * NPT]; // 128 MB
__device__ __align__(1024) __nv_bfloat16 g_Kbl[(size_t)NPT * NPT]; // 128 MB
__device__ __align__(1024) __nv_bfloat16 g_P1[CP * NPT];           // (A_sp p)
__device__ __align__(1024) __nv_bfloat16 g_P2[CP * NPT];           // (A_bl p)
__device__ __align__(256)  float g_part[NSLICE * CP * NPT];        // partials
__device__ float g_hsp[NPT], g_hbl[NPT];
__device__ float g_Asp[NC * NC], g_Abl[NC * NC];

DI float ex2f(float x) { float y; asm("ex2.approx.f32 %0, %1;" : "=f"(y) : "f"(x)); return y; }

DI void mma16816(float* c, const uint32_t* a, uint32_t b0, uint32_t b1) {
    asm volatile(
        "mma.sync.aligned.m16n8k16.row.col.f32.bf16.bf16.f32 "
        "{%0,%1,%2,%3}, {%4,%5,%6,%7}, {%8,%9}, {%0,%1,%2,%3};"
        : "+f"(c[0]), "+f"(c[1]), "+f"(c[2]), "+f"(c[3])
        : "r"(a[0]), "r"(a[1]), "r"(a[2]), "r"(a[3]), "r"(b0), "r"(b1));
}

// ---------------- tiny prep kernels -----------------------------------------
__global__ void k_prepA(const float* __restrict__ Wsp, const float* __restrict__ Wbl,
                        const float* __restrict__ Comp) {
    int t = threadIdx.x;
    if (t < NC * NC) {
        int c = t / NC, c2 = t % NC;
        float s1 = 0.f, s2 = 0.f;
        for (int k = 0; k < NC; k++) {
            s1 += Comp[c * NC + k] * Wsp[k * NC + c2];
            s2 += Comp[c * NC + k] * Wbl[k * NC + c2];
        }
        g_Asp[t] = -s1;
        g_Abl[t] = -s2;
    }
}

__global__ void k_norm(const float* __restrict__ feat) {
    int i = blockIdx.x * 256 + threadIdx.x;
    float f0 = feat[i],           f1 = feat[NPT + i],     f2 = feat[2 * NPT + i];
    float f3 = feat[3 * NPT + i], f4 = feat[4 * NPT + i], f5 = feat[5 * NPT + i];
    float n3 = f0 * f0 + f1 * f1 + f2 * f2;
    float n6 = n3 + f3 * f3 + f4 * f4 + f5 * f5;
    g_hsp[i] = 0.5f * ESP * n3;
    g_hbl[i] = 0.5f * EBL * n6;
}

// ---------------- kernel-matrix builder (fragment-blocked stores) ------------
// CTA: 128 i x 128 j region. 8 warps: warp w -> js_local = w&3, it-group w>>2.
// Thread: fixed i (per round), 8 j's = superchunk base + tq*2 + {0,1,8,9,16,17,24,25}.
__global__ __launch_bounds__(256) void k_pairs(const float* __restrict__ feat) {
    __shared__ float sfi[6][128], sfj[6][128], shs[128], shb[128];
    int t = threadIdx.x;
    int i0 = blockIdx.y * 128, j0 = blockIdx.x * 128;

    for (int v = t; v < 6 * 128; v += 256) {
        int d = v >> 7, x = v & 127;
        sfi[d][x] = feat[d * NPT + i0 + x];
        sfj[d][x] = feat[d * NPT + j0 + x];
    }
    if (t < 128) { shs[t] = g_hsp[i0 + t]; shb[t] = g_hbl[i0 + t]; }
    __syncthreads();

    int w = t >> 5, lane = t & 31;
    int ir = lane >> 2, tq = lane & 3;
    int js_local = w & 3;          // superchunk within 128-j tile
    int itgrp    = w >> 2;         // 0/1

    // this thread's 8 j positions (local to tile)
    int jl[8];
#pragma unroll
    for (int u = 0; u < 8; u++)
        jl[u] = js_local * 32 + tq * 2 + (u & 1) + ((u >> 1) << 3);

    float fj[6][8], hsj[8], hbj[8];
#pragma unroll
    for (int d = 0; d < 6; d++)
#pragma unroll
        for (int u = 0; u < 8; u++) fj[d][u] = sfj[d][jl[u]];
#pragma unroll
    for (int u = 0; u < 8; u++) {
        float n3 = fj[0][u] * fj[0][u] + fj[1][u] * fj[1][u] + fj[2][u] * fj[2][u];
        float n6 = n3 + fj[3][u] * fj[3][u] + fj[4][u] * fj[4][u] + fj[5][u] * fj[5][u];
        hsj[u] = 0.5f * ESP * n3;
        hbj[u] = 0.5f * EBL * n6;
    }

    int js_global = blockIdx.x * 4 + js_local;

#pragma unroll 1
    for (int r = 0; r < 8; r++) {
        int it_local = r * 2 + itgrp;          // 0..15
        int il = it_local * 8 + ir;            // i within tile
        float f0 = sfi[0][il], f1 = sfi[1][il], f2 = sfi[2][il];
        float f3 = sfi[3][il], f4 = sfi[4][il], f5 = sfi[5][il];
        float hs = shs[il], hb = shb[il];

        uint32_t psp[4], pbl[4];
#pragma unroll
        for (int rg = 0; rg < 4; rg++) {
            float vs[2], vb[2];
#pragma unroll
            for (int u2 = 0; u2 < 2; u2++) {
                int u = rg * 2 + u2;
                float d3 = fmaf(f2, fj[2][u], fmaf(f1, fj[1][u], f0 * fj[0][u]));
                float dh = fmaf(f5, fj[5][u], fmaf(f4, fj[4][u], f3 * fj[3][u]));
                float d6 = d3 + dh;
                vs[u2] = ex2f(fmaf(ESP, d3, -(hs + hsj[u])));
                vb[u2] = ex2f(fmaf(EBL, d6, -(hb + hbj[u])));
            }
            __nv_bfloat162 s2 = __floats2bfloat162_rn(vs[0], vs[1]);
            __nv_bfloat162 b2 = __floats2bfloat162_rn(vb[0], vb[1]);
            psp[rg] = *reinterpret_cast<uint32_t*>(&s2);
            pbl[rg] = *reinterpret_cast<uint32_t*>(&b2);
        }
        int it_global = blockIdx.y * 16 + it_local;
        size_t blk = ((size_t)it_global * (NPT / 32) + js_global) * 32 + lane;
        reinterpret_cast<uint4*>(g_Ksp)[blk] = make_uint4(psp[0], psp[1], psp[2], psp[3]);
        reinterpret_cast<uint4*>(g_Kbl)[blk] = make_uint4(pbl[0], pbl[1], pbl[2], pbl[3]);
    }
}

// ---------------- softmax / update / class-vector prep -----------------------
// mode 0: q = unaries               -> write P1,P2
// mode 1: q = unaries + partials    -> write P1,P2
// mode 2: q = unaries + partials    -> write d_out
__global__ __launch_bounds__(128) void k_soft(const float* __restrict__ unaries,
                                              float* __restrict__ out, int mode) {
    __shared__ float sA1[NC * NC], sA2[NC * NC];
    int t = threadIdx.x;
    if (mode != 2) {
        if (t < NC * NC) { sA1[t] = g_Asp[t]; sA2[t] = g_Abl[t]; }
        __syncthreads();
    }
    int i = blockIdx.x * 128 + t;

    float q[NC];
#pragma unroll
    for (int c = 0; c < NC; c++) q[c] = unaries[c * NPT + i];
    if (mode != 0) {
#pragma unroll
        for (int c = 0; c < NC; c++) {
            float s = 0.f;
#pragma unroll
            for (int sl = 0; sl < NSLICE; sl++)
                s += g_part[((size_t)sl * CP + c) * NPT + i];
            q[c] += s;
        }
    }
    if (mode == 2) {
#pragma unroll
        for (int c = 0; c < NC; c++) out[c * NPT + i] = q[c];
        return;
    }
    float m = q[0];
#pragma unroll
    for (int c = 1; c < NC; c++) m = fmaxf(m, q[c]);
    float p[NC], s = 0.f;
#pragma unroll
    for (int c = 0; c < NC; c++) { p[c] = ex2f((q[c] - m) * LOG2E); s += p[c]; }
    float inv = __fdividef(1.0f, s);
#pragma unroll
    for (int c = 0; c < NC; c++) p[c] *= inv;

#pragma unroll
    for (int c16 = 0; c16 < CP; c16++) {
        float v1 = 0.f, v2 = 0.f;
        if (c16 < NC) {
#pragma unroll
            for (int c = 0; c < NC; c++) {
                v1 = fmaf(sA1[c16 * NC + c], p[c], v1);
                v2 = fmaf(sA2[c16 * NC + c], p[c], v2);
            }
        }
        g_P1[c16 * NPT + i] = __float2bfloat16(v1);
        g_P2[c16 * NPT + i] = __float2bfloat16(v2);
    }
}

// ---------------- GEMM: Out[16c x 8192i] += P1*Ksp + P2*Kbl ------------------
// grid (32, NSLICE): x = i-block of 256, y = j slice of 1024.
// 8 warps x 4 n-tiles (8 i each) = 256 i per CTA. Accum fp32 in frags.
__global__ __launch_bounds__(256) void k_gemm() {
    int t = threadIdx.x, w = t >> 5, lane = t & 31;
    int g = lane >> 2, tq = lane & 3;
    int it_base = blockIdx.x * 32 + w * 4;
    int slice = blockIdx.y;

    float acc[4][4] = {};

    const uint4* Ksp4 = reinterpret_cast<const uint4*>(g_Ksp);
    const uint4* Kbl4 = reinterpret_cast<const uint4*>(g_Kbl);

#pragma unroll 1
    for (int sc = 0; sc < 32; sc++) {
        int js = slice * 32 + sc;
        int j0 = js * 32;

        // A fragments for P1/P2: two k16-chunks (j0, j0+16)
        uint32_t A1[2][4], A2[2][4];
#pragma unroll
        for (int ch = 0; ch < 2; ch++) {
            int col = j0 + ch * 16 + tq * 2;
            A1[ch][0] = *reinterpret_cast<const uint32_t*>(&g_P1[(size_t)g * NPT + col]);
            A1[ch][1] = *reinterpret_cast<const uint32_t*>(&g_P1[(size_t)(g + 8) * NPT + col]);
            A1[ch][2] = *reinterpret_cast<const uint32_t*>(&g_P1[(size_t)g * NPT + col + 8]);
            A1[ch][3] = *reinterpret_cast<const uint32_t*>(&g_P1[(size_t)(g + 8) * NPT + col + 8]);
            A2[ch][0] = *reinterpret_cast<const uint32_t*>(&g_P2[(size_t)g * NPT + col]);
            A2[ch][1] = *reinterpret_cast<const uint32_t*>(&g_P2[(size_t)(g + 8) * NPT + col]);
            A2[ch][2] = *reinterpret_cast<const uint32_t*>(&g_P2[(size_t)g * NPT + col + 8]);
            A2[ch][3] = *reinterpret_cast<const uint32_t*>(&g_P2[(size_t)(g + 8) * NPT + col + 8]);
        }

#pragma unroll
        for (int tt = 0; tt < 4; tt++) {
            size_t blk = ((size_t)(it_base + tt) * (NPT / 32) + js) * 32 + lane;
            uint4 Bsp = Ksp4[blk];
            uint4 Bbl = Kbl4[blk];
            mma16816(acc[tt], A1[0], Bsp.x, Bsp.y);
            mma16816(acc[tt], A1[1], Bsp.z, Bsp.w);
            mma16816(acc[tt], A2[0], Bbl.x, Bbl.y);
            mma16816(acc[tt], A2[1], Bbl.z, Bbl.w);
        }
    }

    // epilogue: g_part[slice][c][i], c = {g, g+8}, i = tile*8 + tq*2 + {0,1}
#pragma unroll
    for (int tt = 0; tt < 4; tt++) {
        int i = (it_base + tt) * 8 + tq * 2;
        float2* p0 = reinterpret_cast<float2*>(&g_part[((size_t)slice * CP + g) * NPT + i]);
        float2* p1 = reinterpret_cast<float2*>(&g_part[((size_t)slice * CP + g + 8) * NPT + i]);
        *p0 = make_float2(acc[tt][0], acc[tt][1]);
        *p1 = make_float2(acc[tt][2], acc[tt][3]);
    }
}

// ---------------- launch ------------------------------------------------------
extern "C" void kernel_launch(void* const* d_in, const int* in_sizes, int n_in,
                              void* d_out, int out_size) {
    const float* unaries = (const float*)d_in[0];
    const float* feat    = (const float*)d_in[1];
    const float* Wsp     = (const float*)d_in[2];
    const float* Wbl     = (const float*)d_in[3];
    const float* Comp    = (const float*)d_in[4];
    float* out = (float*)d_out;

    k_prepA<<<1, 128>>>(Wsp, Wbl, Comp);
    k_norm<<<NPT / 256, 256>>>(feat);
    k_pairs<<<dim3(64, 64), 256>>>(feat);
    k_soft<<<NPT / 128, 128>>>(unaries, out, 0);
    for (int it = 0; it < 5; it++) {
        k_gemm<<<dim3(32, NSLICE), 256>>>();
        k_soft<<<NPT / 128, 128>>>(unaries, out, (it == 4) ? 2 : 1);
    }
}

// round 5
// speedup vs baseline: 1.4981x; 1.4981x over previous
#include <cuda_runtime.h>
#include <cuda_bf16.h>
#include <cstdint>

// ============================================================================
// Mean-field CRF on GB300 (plain sm_103 PTX: mma.sync m16n8k16 bf16 path).
// K_sp/K_bl (8192^2, constant over 5 iters) built once in bf16 (fragment-
// blocked layout). Each iteration = ONE fused kernel: phase A computes
// softmax+class-vectors P for the CTA's j-slice into smem (A-fragment layout),
// phase B streams K and runs mma.sync, writing split-K partials.
//   q = unaries + (A_sp p) K_sp + (A_bl p) K_bl,  A_* = -(compat @ W_*)
// ============================================================================

#define DI __device__ __forceinline__

static constexpr int   NPT   = 8192;
static constexpr int   NC    = 10;
static constexpr int   CP    = 16;           // padded classes (mma m16)
static constexpr int   NSL   = 16;           // split-K slices
static constexpr int   JPS   = 512;          // j per slice
static constexpr float LOG2E = 1.4426950408889634f;
static constexpr float ESP   = LOG2E / 64.0f;
static constexpr float EBL   = LOG2E;

// ---- static device scratch (no allocations) --------------------------------
// K fragment-blocked (VERIFIED in R2): block = (i-tile of 8) x (j-chunk of 32)
// = 512 B; uint4 per lane: regs = j offsets tq*2 + {0,1 | 8,9 | 16,17 | 24,25}.
__device__ __align__(1024) __nv_bfloat16 g_Ksp[(size_t)NPT * NPT]; // 128 MB
__device__ __align__(1024) __nv_bfloat16 g_Kbl[(size_t)NPT * NPT]; // 128 MB
__device__ __align__(256)  float g_part[2][(size_t)NSL * CP * NPT]; // 2 x 8.4MB
__device__ float g_hsp[NPT], g_hbl[NPT];
__device__ float g_Asp[NC * NC], g_Abl[NC * NC];

DI float ex2f(float x) { float y; asm("ex2.approx.f32 %0, %1;" : "=f"(y) : "f"(x)); return y; }

DI void mma16816(float* c, const uint32_t* a, uint32_t b0, uint32_t b1) {
    asm volatile(
        "mma.sync.aligned.m16n8k16.row.col.f32.bf16.bf16.f32 "
        "{%0,%1,%2,%3}, {%4,%5,%6,%7}, {%8,%9}, {%0,%1,%2,%3};"
        : "+f"(c[0]), "+f"(c[1]), "+f"(c[2]), "+f"(c[3])
        : "r"(a[0]), "r"(a[1]), "r"(a[2]), "r"(a[3]), "r"(b0), "r"(b1));
}

// ---------------- tiny prep kernels -----------------------------------------
__global__ void k_prepA(const float* __restrict__ Wsp, const float* __restrict__ Wbl,
                        const float* __restrict__ Comp) {
    int t = threadIdx.x;
    if (t < NC * NC) {
        int c = t / NC, c2 = t % NC;
        float s1 = 0.f, s2 = 0.f;
        for (int k = 0; k < NC; k++) {
            s1 += Comp[c * NC + k] * Wsp[k * NC + c2];
            s2 += Comp[c * NC + k] * Wbl[k * NC + c2];
        }
        g_Asp[t] = -s1;
        g_Abl[t] = -s2;
    }
}

__global__ void k_norm(const float* __restrict__ feat) {
    int i = blockIdx.x * 256 + threadIdx.x;
    float f0 = feat[i],           f1 = feat[NPT + i],     f2 = feat[2 * NPT + i];
    float f3 = feat[3 * NPT + i], f4 = feat[4 * NPT + i], f5 = feat[5 * NPT + i];
    float n3 = f0 * f0 + f1 * f1 + f2 * f2;
    float n6 = n3 + f3 * f3 + f4 * f4 + f5 * f5;
    g_hsp[i] = 0.5f * ESP * n3;
    g_hbl[i] = 0.5f * EBL * n6;
}

// ---------------- kernel-matrix builder (verified R2 layout) -----------------
__global__ __launch_bounds__(256) void k_pairs(const float* __restrict__ feat, int yoff) {
    __shared__ float sfi[6][128], sfj[6][128], shs[128], shb[128];
    int t = threadIdx.x;
    int by = blockIdx.y + yoff;
    int i0 = by * 128, j0 = blockIdx.x * 128;

    for (int v = t; v < 6 * 128; v += 256) {
        int d = v >> 7, x = v & 127;
        sfi[d][x] = feat[d * NPT + i0 + x];
        sfj[d][x] = feat[d * NPT + j0 + x];
    }
    if (t < 128) { shs[t] = g_hsp[i0 + t]; shb[t] = g_hbl[i0 + t]; }
    __syncthreads();

    int w = t >> 5, lane = t & 31;
    int ir = lane >> 2, tq = lane & 3;
    int js_local = w & 3;
    int itgrp    = w >> 2;

    int jl[8];
#pragma unroll
    for (int u = 0; u < 8; u++)
        jl[u] = js_local * 32 + tq * 2 + (u & 1) + ((u >> 1) << 3);

    float fj[6][8], hsj[8], hbj[8];
#pragma unroll
    for (int d = 0; d < 6; d++)
#pragma unroll
        for (int u = 0; u < 8; u++) fj[d][u] = sfj[d][jl[u]];
#pragma unroll
    for (int u = 0; u < 8; u++) {
        float n3 = fj[0][u] * fj[0][u] + fj[1][u] * fj[1][u] + fj[2][u] * fj[2][u];
        float n6 = n3 + fj[3][u] * fj[3][u] + fj[4][u] * fj[4][u] + fj[5][u] * fj[5][u];
        hsj[u] = 0.5f * ESP * n3;
        hbj[u] = 0.5f * EBL * n6;
    }

    int js_global = by * 0 + blockIdx.x * 4 + js_local;

#pragma unroll 1
    for (int r = 0; r < 8; r++) {
        int it_local = r * 2 + itgrp;
        int il = it_local * 8 + ir;
        float f0 = sfi[0][il], f1 = sfi[1][il], f2 = sfi[2][il];
        float f3 = sfi[3][il], f4 = sfi[4][il], f5 = sfi[5][il];
        float hs = shs[il], hb = shb[il];

        uint32_t psp[4], pbl[4];
#pragma unroll
        for (int rg = 0; rg < 4; rg++) {
            float vs[2], vb[2];
#pragma unroll
            for (int u2 = 0; u2 < 2; u2++) {
                int u = rg * 2 + u2;
                float d3 = fmaf(f2, fj[2][u], fmaf(f1, fj[1][u], f0 * fj[0][u]));
                float dh = fmaf(f5, fj[5][u], fmaf(f4, fj[4][u], f3 * fj[3][u]));
                float d6 = d3 + dh;
                vs[u2] = ex2f(fmaf(ESP, d3, -(hs + hsj[u])));
                vb[u2] = ex2f(fmaf(EBL, d6, -(hb + hbj[u])));
            }
            __nv_bfloat162 s2 = __floats2bfloat162_rn(vs[0], vs[1]);
            __nv_bfloat162 b2 = __floats2bfloat162_rn(vb[0], vb[1]);
            psp[rg] = *reinterpret_cast<uint32_t*>(&s2);
            pbl[rg] = *reinterpret_cast<uint32_t*>(&b2);
        }
        int it_global = by * 16 + it_local;
        size_t blk = ((size_t)it_global * (NPT / 32) + js_global) * 32 + lane;
        reinterpret_cast<uint4*>(g_Ksp)[blk] = make_uint4(psp[0], psp[1], psp[2], psp[3]);
        reinterpret_cast<uint4*>(g_Kbl)[blk] = make_uint4(pbl[0], pbl[1], pbl[2], pbl[3]);
    }
}

// ---------------- fused softmax + GEMM ---------------------------------------
// grid (32, NSL): CTA = 256 i (8 warps x 4 i-tiles) x one 512-j slice.
// Phase A: P fragments for the slice -> smem.  Phase B: stream K, mma.sync.
__global__ __launch_bounds__(256, 4) void k_gemm(const float* __restrict__ unaries,
                                                 int first, int wbuf) {
    __shared__ uint4 sA1[32 * 32];     // [ks within slice][lane] : 16KB
    __shared__ uint4 sA2[32 * 32];     // 16KB
    __shared__ float sW1[NC * NC], sW2[NC * NC];

    int t = threadIdx.x;
    int slice = blockIdx.y;

    for (int v = t; v < NC * NC; v += 256) { sW1[v] = g_Asp[v]; sW2[v] = g_Abl[v]; }
    __syncthreads();

    // ---------- phase A: this thread owns points j, j+1 ----------------------
    {
        int j = slice * JPS + t * 2;
        float q0[NC], q1[NC];
#pragma unroll
        for (int c = 0; c < NC; c++) {
            float2 u = *reinterpret_cast<const float2*>(&unaries[(size_t)c * NPT + j]);
            q0[c] = u.x; q1[c] = u.y;
        }
        if (!first) {
            const float* pb = g_part[wbuf ^ 1];
#pragma unroll
            for (int sl = 0; sl < NSL; sl++)
#pragma unroll
                for (int c = 0; c < NC; c++) {
                    float2 v = *reinterpret_cast<const float2*>(
                        &pb[((size_t)sl * CP + c) * NPT + j]);
                    q0[c] += v.x; q1[c] += v.y;
                }
        }
        float p0[NC], p1[NC];
        {
            float m0 = q0[0], m1 = q1[0];
#pragma unroll
            for (int c = 1; c < NC; c++) { m0 = fmaxf(m0, q0[c]); m1 = fmaxf(m1, q1[c]); }
            float s0 = 0.f, s1 = 0.f;
#pragma unroll
            for (int c = 0; c < NC; c++) {
                p0[c] = ex2f((q0[c] - m0) * LOG2E); s0 += p0[c];
                p1[c] = ex2f((q1[c] - m1) * LOG2E); s1 += p1[c];
            }
            float i0 = __fdividef(1.f, s0), i1 = __fdividef(1.f, s1);
#pragma unroll
            for (int c = 0; c < NC; c++) { p0[c] *= i0; p1[c] *= i1; }
        }
        // scatter into A-fragment layout
        int ks = t >> 3;
        int tq = t & 3;
        int hik = ((t & 7) >= 4) ? 2 : 0;
#pragma unroll
        for (int c16 = 0; c16 < CP; c16++) {
            float a0 = 0.f, a1 = 0.f, b0 = 0.f, b1 = 0.f;
            if (c16 < NC) {
#pragma unroll
                for (int c = 0; c < NC; c++) {
                    float w1 = sW1[c16 * NC + c], w2 = sW2[c16 * NC + c];
                    a0 = fmaf(w1, p0[c], a0); a1 = fmaf(w1, p1[c], a1);
                    b0 = fmaf(w2, p0[c], b0); b1 = fmaf(w2, p1[c], b1);
                }
            }
            int lane = (c16 & 7) * 4 + tq;
            int reg  = ((c16 >= 8) ? 1 : 0) + hik;
            __nv_bfloat162 v1 = __floats2bfloat162_rn(a0, a1);
            __nv_bfloat162 v2 = __floats2bfloat162_rn(b0, b1);
            reinterpret_cast<uint32_t*>(&sA1[ks * 32 + lane])[reg] =
                *reinterpret_cast<uint32_t*>(&v1);
            reinterpret_cast<uint32_t*>(&sA2[ks * 32 + lane])[reg] =
                *reinterpret_cast<uint32_t*>(&v2);
        }
    }
    __syncthreads();

    // ---------- phase B: GEMM over this slice's 16 chunks of 32 j ------------
    int w = t >> 5, lane = t & 31, g = lane >> 2, tq = lane & 3;
    int itb = blockIdx.x * 32 + w * 4;     // 8-i tile index base

    float acc[4][4] = {};
    const uint4* Ksp4 = reinterpret_cast<const uint4*>(g_Ksp);
    const uint4* Kbl4 = reinterpret_cast<const uint4*>(g_Kbl);

#pragma unroll 2
    for (int cs = 0; cs < 16; cs++) {
        int js = slice * 16 + cs;
        uint4 a10 = sA1[(cs * 2) * 32 + lane];
        uint4 a11 = sA1[(cs * 2 + 1) * 32 + lane];
        uint4 a20 = sA2[(cs * 2) * 32 + lane];
        uint4 a21 = sA2[(cs * 2 + 1) * 32 + lane];
#pragma unroll
        for (int tt = 0; tt < 4; tt++) {
            size_t blk = ((size_t)(itb + tt) * (NPT / 32) + js) * 32 + lane;
            uint4 Bs = Ksp4[blk];
            uint4 Bb = Kbl4[blk];
            mma16816(acc[tt], reinterpret_cast<uint32_t*>(&a10), Bs.x, Bs.y);
            mma16816(acc[tt], reinterpret_cast<uint32_t*>(&a11), Bs.z, Bs.w);
            mma16816(acc[tt], reinterpret_cast<uint32_t*>(&a20), Bb.x, Bb.y);
            mma16816(acc[tt], reinterpret_cast<uint32_t*>(&a21), Bb.z, Bb.w);
        }
    }

    float* pw = g_part[wbuf];
#pragma unroll
    for (int tt = 0; tt < 4; tt++) {
        int i = (itb + tt) * 8 + tq * 2;
        *reinterpret_cast<float2*>(&pw[((size_t)slice * CP + g) * NPT + i]) =
            make_float2(acc[tt][0], acc[tt][1]);
        *reinterpret_cast<float2*>(&pw[((size_t)slice * CP + g + 8) * NPT + i]) =
            make_float2(acc[tt][2], acc[tt][3]);
    }
}

// ---------------- final output -----------------------------------------------
__global__ __launch_bounds__(128) void k_out(const float* __restrict__ unaries,
                                             float* __restrict__ out, int buf) {
    int i = blockIdx.x * 128 + threadIdx.x;
    const float* pb = g_part[buf];
#pragma unroll
    for (int c = 0; c < NC; c++) {
        float q = unaries[(size_t)c * NPT + i];
#pragma unroll
        for (int sl = 0; sl < NSL; sl++)
            q += pb[((size_t)sl * CP + c) * NPT + i];
        out[(size_t)c * NPT + i] = q;
    }
}

// ---------------- launch ------------------------------------------------------
extern "C" void kernel_launch(void* const* d_in, const int* in_sizes, int n_in,
                              void* d_out, int out_size) {
    const float* unaries = (const float*)d_in[0];
    const float* feat    = (const float*)d_in[1];
    const float* Wsp     = (const float*)d_in[2];
    const float* Wbl     = (const float*)d_in[3];
    const float* Comp    = (const float*)d_in[4];
    float* out = (float*)d_out;

    k_prepA<<<1, 128>>>(Wsp, Wbl, Comp);          // 0
    k_norm<<<NPT / 256, 256>>>(feat);             // 1
    k_pairs<<<dim3(64, 32), 256>>>(feat, 0);      // 2
    k_pairs<<<dim3(64, 32), 256>>>(feat, 32);     // 3
    for (int it = 0; it < 5; it++)                // 4..8 (launch 5 = iter 1)
        k_gemm<<<dim3(32, NSL), 256>>>(unaries, it == 0 ? 1 : 0, it & 1);
    k_out<<<NPT / 128, 128>>>(unaries, out, 0);   // iter4 wrote buf 0
}

// round 6
// speedup vs baseline: 1.5802x; 1.0548x over previous
#include <cuda_runtime.h>
#include <cuda_bf16.h>
#include <cstdint>

// ============================================================================
// Mean-field CRF on GB300 (plain sm_103 PTX: mma.sync m16n8k16 bf16 path).
// K_sp/K_bl (8192^2, constant over 5 iters) built once in bf16, fragment-
// blocked; builder exploits K symmetry (upper-triangle tiles + smem-transposed
// mirror stores) to halve the MUFU-bound exp work. Each iteration is ONE fused
// kernel: phase A computes softmax+class-vectors for the CTA's j-slice into
// smem (mma A-fragment layout), phase B streams K via mma.sync -> partials.
//   q = unaries + (A_sp p) K_sp + (A_bl p) K_bl,  A_* = -(compat @ W_*)
// ============================================================================

#define DI __device__ __forceinline__

static constexpr int   NPT   = 8192;
static constexpr int   NC    = 10;
static constexpr int   CP    = 16;           // padded classes (mma m16)
static constexpr int   NSL   = 16;           // split-K slices
static constexpr int   JPS   = 512;          // j per slice
static constexpr float LOG2E = 1.4426950408889634f;
static constexpr float ESP   = LOG2E / 64.0f;
static constexpr float EBL   = LOG2E;

static constexpr int MPITCH = 136;           // smem mirror pitch (bank-safe)
static constexpr int SMEM_MIRROR = 2 * 128 * MPITCH * 2;  // 69632 B

// ---- static device scratch (no allocations) --------------------------------
// K fragment-blocked: block = (i-tile of 8) x (j-chunk of 32) = 512 B;
// uint4 per lane(ir*4+tq): reg rg, half b <-> j offset tq*2 + b + rg*8.
__device__ __align__(1024) __nv_bfloat16 g_Ksp[(size_t)NPT * NPT]; // 128 MB
__device__ __align__(1024) __nv_bfloat16 g_Kbl[(size_t)NPT * NPT]; // 128 MB
__device__ __align__(256)  float g_part[2][(size_t)NSL * CP * NPT];
__device__ float g_hsp[NPT], g_hbl[NPT];
__device__ float g_Asp[NC * NC], g_Abl[NC * NC];

DI float ex2f(float x) { float y; asm("ex2.approx.f32 %0, %1;" : "=f"(y) : "f"(x)); return y; }

DI void mma16816(float* c, const uint32_t* a, uint32_t b0, uint32_t b1) {
    asm volatile(
        "mma.sync.aligned.m16n8k16.row.col.f32.bf16.bf16.f32 "
        "{%0,%1,%2,%3}, {%4,%5,%6,%7}, {%8,%9}, {%0,%1,%2,%3};"
        : "+f"(c[0]), "+f"(c[1]), "+f"(c[2]), "+f"(c[3])
        : "r"(a[0]), "r"(a[1]), "r"(a[2]), "r"(a[3]), "r"(b0), "r"(b1));
}

// ---------------- tiny prep kernels -----------------------------------------
__global__ void k_prepA(const float* __restrict__ Wsp, const float* __restrict__ Wbl,
                        const float* __restrict__ Comp) {
    int t = threadIdx.x;
    if (t < NC * NC) {
        int c = t / NC, c2 = t % NC;
        float s1 = 0.f, s2 = 0.f;
        for (int k = 0; k < NC; k++) {
            s1 += Comp[c * NC + k] * Wsp[k * NC + c2];
            s2 += Comp[c * NC + k] * Wbl[k * NC + c2];
        }
        g_Asp[t] = -s1;
        g_Abl[t] = -s2;
    }
}

__global__ void k_norm(const float* __restrict__ feat) {
    int i = blockIdx.x * 256 + threadIdx.x;
    float f0 = feat[i],           f1 = feat[NPT + i],     f2 = feat[2 * NPT + i];
    float f3 = feat[3 * NPT + i], f4 = feat[4 * NPT + i], f5 = feat[5 * NPT + i];
    float n3 = f0 * f0 + f1 * f1 + f2 * f2;
    float n6 = n3 + f3 * f3 + f4 * f4 + f5 * f5;
    g_hsp[i] = 0.5f * ESP * n3;
    g_hbl[i] = 0.5f * EBL * n6;
}

// ---------------- symmetric kernel-matrix builder ----------------------------
// Upper-triangle tiles only (bi <= bj); each CTA computes its 128x128 tile,
// stores forward fragment blocks from regs, stages the tile in smem, and
// (off-diagonal) emits the mirrored tile's blocks via a transposed gather.
__global__ __launch_bounds__(256) void k_pairs(const float* __restrict__ feat) {
    int bi = blockIdx.y, bj = blockIdx.x;
    if (bj < bi) return;

    extern __shared__ uint16_t smir[];          // ssp[128][136], sbl[128][136]
    uint16_t* ssp = smir;
    uint16_t* sbl = smir + 128 * MPITCH;
    __shared__ float sfi[6][128], sfj[6][128], shs[128], shb[128];

    int t = threadIdx.x;
    int i0 = bi * 128, j0 = bj * 128;

    for (int v = t; v < 6 * 128; v += 256) {
        int d = v >> 7, x = v & 127;
        sfi[d][x] = feat[d * NPT + i0 + x];
        sfj[d][x] = feat[d * NPT + j0 + x];
    }
    if (t < 128) { shs[t] = g_hsp[i0 + t]; shb[t] = g_hbl[i0 + t]; }
    __syncthreads();

    int w = t >> 5, lane = t & 31;
    int ir = lane >> 2, tq = lane & 3;
    int js_local = w & 3;
    int itgrp    = w >> 2;

    int jl[8];
#pragma unroll
    for (int u = 0; u < 8; u++)
        jl[u] = js_local * 32 + tq * 2 + (u & 1) + ((u >> 1) << 3);

    float fj[6][8], hsj[8], hbj[8];
#pragma unroll
    for (int d = 0; d < 6; d++)
#pragma unroll
        for (int u = 0; u < 8; u++) fj[d][u] = sfj[d][jl[u]];
#pragma unroll
    for (int u = 0; u < 8; u++) {
        float n3 = fj[0][u] * fj[0][u] + fj[1][u] * fj[1][u] + fj[2][u] * fj[2][u];
        float n6 = n3 + fj[3][u] * fj[3][u] + fj[4][u] * fj[4][u] + fj[5][u] * fj[5][u];
        hsj[u] = 0.5f * ESP * n3;
        hbj[u] = 0.5f * EBL * n6;
    }

    int js_global = bj * 4 + js_local;

#pragma unroll 1
    for (int r = 0; r < 8; r++) {
        int it_local = r * 2 + itgrp;
        int il = it_local * 8 + ir;
        float f0 = sfi[0][il], f1 = sfi[1][il], f2 = sfi[2][il];
        float f3 = sfi[3][il], f4 = sfi[4][il], f5 = sfi[5][il];
        float hs = shs[il], hb = shb[il];

        uint32_t psp[4], pbl[4];
#pragma unroll
        for (int rg = 0; rg < 4; rg++) {
            float vs[2], vb[2];
#pragma unroll
            for (int u2 = 0; u2 < 2; u2++) {
                int u = rg * 2 + u2;
                float d3 = fmaf(f2, fj[2][u], fmaf(f1, fj[1][u], f0 * fj[0][u]));
                float dh = fmaf(f5, fj[5][u], fmaf(f4, fj[4][u], f3 * fj[3][u]));
                float d6 = d3 + dh;
                vs[u2] = ex2f(fmaf(ESP, d3, -(hs + hsj[u])));
                vb[u2] = ex2f(fmaf(EBL, d6, -(hb + hbj[u])));
            }
            __nv_bfloat162 s2 = __floats2bfloat162_rn(vs[0], vs[1]);
            __nv_bfloat162 b2 = __floats2bfloat162_rn(vb[0], vb[1]);
            psp[rg] = *reinterpret_cast<uint32_t*>(&s2);
            pbl[rg] = *reinterpret_cast<uint32_t*>(&b2);
        }
        int it_global = bi * 16 + it_local;
        size_t blk = ((size_t)it_global * (NPT / 32) + js_global) * 32 + lane;
        reinterpret_cast<uint4*>(g_Ksp)[blk] = make_uint4(psp[0], psp[1], psp[2], psp[3]);
        reinterpret_cast<uint4*>(g_Kbl)[blk] = make_uint4(pbl[0], pbl[1], pbl[2], pbl[3]);

        // stage into smem tile: row il, cols js_local*32 + rg*8 + tq*2 + {0,1}
        int ro = il * MPITCH + js_local * 32 + tq * 2;
#pragma unroll
        for (int rg = 0; rg < 4; rg++) {
            *reinterpret_cast<uint32_t*>(&ssp[ro + rg * 8]) = psp[rg];
            *reinterpret_cast<uint32_t*>(&sbl[ro + rg * 8]) = pbl[rg];
        }
    }
    __syncthreads();

    if (bi == bj) return;

    // mirror tile (bj,bi): value(lane,rg,b) = K[y,x] = s[a][c],
    // a = 32*js_local + tq*2 + b + rg*8 (rows), c = 8*it_m + ir (col).
#pragma unroll 1
    for (int r = 0; r < 8; r++) {
        int it_m = r * 2 + itgrp;
        int c = it_m * 8 + ir;
        uint32_t qsp[4], qbl[4];
#pragma unroll
        for (int rg = 0; rg < 4; rg++) {
            int a0 = js_local * 32 + tq * 2 + rg * 8;
            uint32_t s_lo = ssp[a0 * MPITCH + c];
            uint32_t s_hi = ssp[(a0 + 1) * MPITCH + c];
            qsp[rg] = s_lo | (s_hi << 16);
            uint32_t b_lo = sbl[a0 * MPITCH + c];
            uint32_t b_hi = sbl[(a0 + 1) * MPITCH + c];
            qbl[rg] = b_lo | (b_hi << 16);
        }
        int itg = bj * 16 + it_m;
        int jsg = bi * 4 + js_local;
        size_t blk = ((size_t)itg * (NPT / 32) + jsg) * 32 + lane;
        reinterpret_cast<uint4*>(g_Ksp)[blk] = make_uint4(qsp[0], qsp[1], qsp[2], qsp[3]);
        reinterpret_cast<uint4*>(g_Kbl)[blk] = make_uint4(qbl[0], qbl[1], qbl[2], qbl[3]);
    }
}

// ---------------- fused softmax + GEMM ---------------------------------------
// grid (16, NSL): CTA = 512 i (8 warps x 8 i-tiles) x one 512-j slice.
__global__ __launch_bounds__(256, 2) void k_gemm(const float* __restrict__ unaries,
                                                 int first, int wbuf) {
    __shared__ uint4 sA1[32 * 32];     // 16KB : [ks within slice][lane]
    __shared__ uint4 sA2[32 * 32];     // 16KB
    __shared__ float sW1[NC * NC], sW2[NC * NC];

    int t = threadIdx.x;
    int slice = blockIdx.y;

    for (int v = t; v < NC * NC; v += 256) { sW1[v] = g_Asp[v]; sW2[v] = g_Abl[v]; }
    __syncthreads();

    // ---------- phase A: this thread owns points j, j+1 ----------------------
    {
        int j = slice * JPS + t * 2;
        float q0[NC], q1[NC];
#pragma unroll
        for (int c = 0; c < NC; c++) {
            float2 u = *reinterpret_cast<const float2*>(&unaries[(size_t)c * NPT + j]);
            q0[c] = u.x; q1[c] = u.y;
        }
        if (!first) {
            const float* pb = g_part[wbuf ^ 1];
#pragma unroll
            for (int sl = 0; sl < NSL; sl++)
#pragma unroll
                for (int c = 0; c < NC; c++) {
                    float2 v = *reinterpret_cast<const float2*>(
                        &pb[((size_t)sl * CP + c) * NPT + j]);
                    q0[c] += v.x; q1[c] += v.y;
                }
        }
        float p0[NC], p1[NC];
        {
            float m0 = q0[0], m1 = q1[0];
#pragma unroll
            for (int c = 1; c < NC; c++) { m0 = fmaxf(m0, q0[c]); m1 = fmaxf(m1, q1[c]); }
            float s0 = 0.f, s1 = 0.f;
#pragma unroll
            for (int c = 0; c < NC; c++) {
                p0[c] = ex2f((q0[c] - m0) * LOG2E); s0 += p0[c];
                p1[c] = ex2f((q1[c] - m1) * LOG2E); s1 += p1[c];
            }
            float i0 = __fdividef(1.f, s0), i1 = __fdividef(1.f, s1);
#pragma unroll
            for (int c = 0; c < NC; c++) { p0[c] *= i0; p1[c] *= i1; }
        }
        int ks = t >> 3;
        int tq = t & 3;
        int hik = ((t & 7) >= 4) ? 2 : 0;
#pragma unroll
        for (int c16 = 0; c16 < CP; c16++) {
            float a0 = 0.f, a1 = 0.f, b0 = 0.f, b1 = 0.f;
            if (c16 < NC) {
#pragma unroll
                for (int c = 0; c < NC; c++) {
                    float w1 = sW1[c16 * NC + c], w2 = sW2[c16 * NC + c];
                    a0 = fmaf(w1, p0[c], a0); a1 = fmaf(w1, p1[c], a1);
                    b0 = fmaf(w2, p0[c], b0); b1 = fmaf(w2, p1[c], b1);
                }
            }
            int lane = (c16 & 7) * 4 + tq;
            int reg  = ((c16 >= 8) ? 1 : 0) + hik;
            __nv_bfloat162 v1 = __floats2bfloat162_rn(a0, a1);
            __nv_bfloat162 v2 = __floats2bfloat162_rn(b0, b1);
            reinterpret_cast<uint32_t*>(&sA1[ks * 32 + lane])[reg] =
                *reinterpret_cast<uint32_t*>(&v1);
            reinterpret_cast<uint32_t*>(&sA2[ks * 32 + lane])[reg] =
                *reinterpret_cast<uint32_t*>(&v2);
        }
    }
    __syncthreads();

    // ---------- phase B: stream K, 8 i-tiles per warp -------------------------
    int w = t >> 5, lane = t & 31, g = lane >> 2, tq = lane & 3;
    int itb = blockIdx.x * 64 + w * 8;

    float acc[8][4] = {};
    const uint4* Ksp4 = reinterpret_cast<const uint4*>(g_Ksp);
    const uint4* Kbl4 = reinterpret_cast<const uint4*>(g_Kbl);

#pragma unroll 1
    for (int cs = 0; cs < 16; cs++) {
        int js = slice * 16 + cs;
        uint4 a10 = sA1[(cs * 2) * 32 + lane];
        uint4 a11 = sA1[(cs * 2 + 1) * 32 + lane];
        uint4 a20 = sA2[(cs * 2) * 32 + lane];
        uint4 a21 = sA2[(cs * 2 + 1) * 32 + lane];
#pragma unroll
        for (int tt = 0; tt < 8; tt++) {
            size_t blk = ((size_t)(itb + tt) * (NPT / 32) + js) * 32 + lane;
            uint4 Bs = Ksp4[blk];
            uint4 Bb = Kbl4[blk];
            mma16816(acc[tt], reinterpret_cast<uint32_t*>(&a10), Bs.x, Bs.y);
            mma16816(acc[tt], reinterpret_cast<uint32_t*>(&a11), Bs.z, Bs.w);
            mma16816(acc[tt], reinterpret_cast<uint32_t*>(&a20), Bb.x, Bb.y);
            mma16816(acc[tt], reinterpret_cast<uint32_t*>(&a21), Bb.z, Bb.w);
        }
    }

    float* pw = g_part[wbuf];
#pragma unroll
    for (int tt = 0; tt < 8; tt++) {
        int i = (itb + tt) * 8 + tq * 2;
        *reinterpret_cast<float2*>(&pw[((size_t)slice * CP + g) * NPT + i]) =
            make_float2(acc[tt][0], acc[tt][1]);
        *reinterpret_cast<float2*>(&pw[((size_t)slice * CP + g + 8) * NPT + i]) =
            make_float2(acc[tt][2], acc[tt][3]);
    }
}

// ---------------- final output -----------------------------------------------
__global__ __launch_bounds__(128) void k_out(const float* __restrict__ unaries,
                                             float* __restrict__ out, int buf) {
    int i = blockIdx.x * 128 + threadIdx.x;
    const float* pb = g_part[buf];
#pragma unroll
    for (int c = 0; c < NC; c++) {
        float q = unaries[(size_t)c * NPT + i];
#pragma unroll
        for (int sl = 0; sl < NSL; sl++)
            q += pb[((size_t)sl * CP + c) * NPT + i];
        out[(size_t)c * NPT + i] = q;
    }
}

// ---------------- launch ------------------------------------------------------
extern "C" void kernel_launch(void* const* d_in, const int* in_sizes, int n_in,
                              void* d_out, int out_size) {
    const float* unaries = (const float*)d_in[0];
    const float* feat    = (const float*)d_in[1];
    const float* Wsp     = (const float*)d_in[2];
    const float* Wbl     = (const float*)d_in[3];
    const float* Comp    = (const float*)d_in[4];
    float* out = (float*)d_out;

    cudaFuncSetAttribute(k_pairs, cudaFuncAttributeMaxDynamicSharedMemorySize,
                         SMEM_MIRROR);

    k_prepA<<<1, 128>>>(Wsp, Wbl, Comp);                    // 0
    k_norm<<<NPT / 256, 256>>>(feat);                       // 1
    k_pairs<<<dim3(64, 64), 256, SMEM_MIRROR>>>(feat);      // 2
    for (int it = 0; it < 5; it++)                          // 3..7 (5 = iter 2)
        k_gemm<<<dim3(16, NSL), 256>>>(unaries, it == 0 ? 1 : 0, it & 1);
    k_out<<<NPT / 128, 128>>>(unaries, out, 0);             // iter4 wrote buf 0
}